// round 7
// baseline (speedup 1.0000x reference)
#include <cuda_runtime.h>
#include <cuda_bf16.h>
#include <math.h>
#include <stdint.h>

// Problem constants
#define BB   16
#define LL   1024
#define DD   768
#define HH   4
#define CC   256
#define EE   8192
#define HC   1024           // H*C
#define EL   (EE + LL)      // 9216 edges incl. self loops
#define KOUT (DD + HC)      // 1792
#define MM   (BB * LL)      // 16384

// ---------------- scratch (device globals; no allocation allowed) -----------
__device__ __align__(16) float g_h   [(size_t)MM * HC];   // h = x @ Wg^T (fp32)
__device__ __align__(16) float g_xr  [(size_t)MM * DD];   // tf32-rounded x
__device__ __align__(16) float g_gatr[(size_t)MM * HC];   // tf32-rounded (gat + b_gat)
__device__ __align__(16) float g_wgr [(size_t)HC * DD];   // tf32-rounded W_gat
__device__ __align__(16) float g_wor [(size_t)DD * KOUT]; // tf32-rounded W_out
__device__ __align__(16) float g_as  [MM * HH];
__device__ __align__(16) float g_ad  [MM * HH];
__device__ __align__(16) float g_max [MM * HH];
__device__ __align__(16) float g_den [MM * HH];
__device__ __align__(16) float g_ebuf[BB * EL * HH];      // per-edge probs
__device__ int g_deg[MM];
__device__ int g_off[MM + 1];
__device__ int g_cur[MM];
__device__ int g_csr[BB * EL];     // packed (eid<<10 | src)

// ---------------- helpers ----------------------------------------------------
__device__ __forceinline__ void redAdd4(float* p, float4 v) {
    asm volatile("red.global.add.v4.f32 [%0], {%1,%2,%3,%4};"
                 :: "l"(p), "f"(v.x), "f"(v.y), "f"(v.z), "f"(v.w) : "memory");
}
__device__ __forceinline__ float tf32r(float x) {
    uint32_t u;
    asm("cvt.rna.tf32.f32 %0, %1;" : "=r"(u) : "f"(x));
    return __uint_as_float(u);
}
__device__ __forceinline__ void cp16s(uint32_t sa, const void* g) {
    asm volatile("cp.async.cg.shared.global [%0], [%1], 16;" :: "r"(sa), "l"(g));
}
__device__ __forceinline__ void mma8(float* d, const uint32_t* a, const uint32_t* b) {
    asm volatile(
        "mma.sync.aligned.m16n8k8.row.col.f32.tf32.tf32.f32 "
        "{%0,%1,%2,%3}, {%4,%5,%6,%7}, {%8,%9}, {%0,%1,%2,%3};"
        : "+f"(d[0]), "+f"(d[1]), "+f"(d[2]), "+f"(d[3])
        : "r"(a[0]), "r"(a[1]), "r"(a[2]), "r"(a[3]), "r"(b[0]), "r"(b[1]));
}

// =================== tf32 mma.sync GEMM, 3-stage cp.async ====================
// C[M,N] = A[M,K] * B[N,K]^T (+bias). 128x128 CTA tile, K chunks of 32.
// 8 warps, warp tile 64x32. SPLIT: virtual concat A at K1 (chunk-aligned).
// ATTN: fuse a_s/a_d = h . att_src/att_dst into the epilogue.
#define LDT   36
#define TILEF (128 * LDT)                 // floats per (A or B) tile
#define STGF  (2 * TILEF)                 // floats per stage
#define STGB  (STGF * 4)                  // bytes per stage (36864)
#define GEMM_SMEM (3 * STGB)              // 110592

template<bool SPLIT, bool ATTN>
__global__ void __launch_bounds__(256)
gemm_mma(const float* __restrict__ A, const float* __restrict__ A2,
         const float* __restrict__ Bm, const float* __restrict__ bias,
         const float* __restrict__ att_s, const float* __restrict__ att_d,
         float* __restrict__ C, int N, int K, int K1)
{
    extern __shared__ float sm[];
    const uint32_t sb = (uint32_t)__cvta_generic_to_shared(sm);

    const int tid  = threadIdx.x;
    const int bm   = blockIdx.y * 128;
    const int bn   = blockIdx.x * 128;
    const int lane = tid & 31;
    const int warp = tid >> 5;
    const int wm   = warp & 1;
    const int wn   = warp >> 1;
    const int lr   = lane >> 2;
    const int lc   = lane & 3;

    float acc[4][4][4];
#pragma unroll
    for (int i = 0; i < 4; i++)
#pragma unroll
        for (int j = 0; j < 4; j++)
#pragma unroll
            for (int r = 0; r < 4; r++) acc[i][j][r] = 0.f;

    const int nk = K >> 5;

    auto load_chunk = [&](int st, int kt) {
        const int k0 = kt << 5;
        const float* Ap; int lda, kc;
        if (!SPLIT || k0 < K1) { Ap = A;  lda = SPLIT ? K1 : K; kc = k0; }
        else                   { Ap = A2; lda = K - K1;         kc = k0 - K1; }
        const uint32_t sa = sb + st * STGB;
        const uint32_t sB = sa + TILEF * 4;
#pragma unroll
        for (int t = 0; t < 4; t++) {
            int fid = tid + t * 256;
            int row = fid >> 3;
            int kq  = (fid & 7) << 2;
            uint32_t so = (uint32_t)(row * LDT + kq) * 4u;
            cp16s(sa + so, &Ap[(size_t)(bm + row) * lda + kc + kq]);
            cp16s(sB + so, &Bm[(size_t)(bn + row) * K + k0 + kq]);
        }
    };

    auto compute = [&](int st) {
        const float* sA = sm + st * STGF + (wm * 64 + lr) * LDT + lc;
        const float* sB = sm + st * STGF + TILEF + (wn * 32 + lr) * LDT + lc;
#pragma unroll
        for (int ks = 0; ks < 32; ks += 8) {
            uint32_t af[4][4], bf[4][2];
#pragma unroll
            for (int i = 0; i < 4; i++) {
                const float* p = sA + i * 16 * LDT + ks;
                af[i][0] = __float_as_uint(p[0]);
                af[i][1] = __float_as_uint(p[8 * LDT]);
                af[i][2] = __float_as_uint(p[4]);
                af[i][3] = __float_as_uint(p[8 * LDT + 4]);
            }
#pragma unroll
            for (int j = 0; j < 4; j++) {
                const float* p = sB + j * 8 * LDT + ks;
                bf[j][0] = __float_as_uint(p[0]);
                bf[j][1] = __float_as_uint(p[4]);
            }
#pragma unroll
            for (int i = 0; i < 4; i++)
#pragma unroll
                for (int j = 0; j < 4; j++)
                    mma8(acc[i][j], af[i], bf[j]);
        }
    };

    // 3-stage pipeline, one barrier per chunk (load stage never == read stage)
    load_chunk(0, 0);
    asm volatile("cp.async.commit_group;");
    load_chunk(1, 1);
    asm volatile("cp.async.commit_group;");

    int cs = 0, ls = 2;
    for (int it = 0; it < nk; ++it) {
        asm volatile("cp.async.wait_group 1;");
        __syncthreads();
        if (it + 2 < nk) load_chunk(ls, it + 2);
        asm volatile("cp.async.commit_group;");
        compute(cs);
        if (++cs == 3) cs = 0;
        if (++ls == 3) ls = 0;
    }

    // ---- epilogue: C write (+bias) ----
#pragma unroll
    for (int j = 0; j < 4; j++) {
        int col = bn + wn * 32 + j * 8 + lc * 2;
        float b0 = bias ? bias[col] : 0.f;
        float b1 = bias ? bias[col + 1] : 0.f;
#pragma unroll
        for (int i = 0; i < 4; i++) {
            int row0 = bm + wm * 64 + i * 16 + lr;
            float2 v0 = make_float2(acc[i][j][0] + b0, acc[i][j][1] + b1);
            float2 v1 = make_float2(acc[i][j][2] + b0, acc[i][j][3] + b1);
            *(float2*)&C[(size_t)row0 * N + col]       = v0;
            *(float2*)&C[(size_t)(row0 + 8) * N + col] = v1;
        }
    }

    // ---- fused attention dots: a_s/a_d partials over this warp's 32 cols ----
    if (ATTN) {
        const int colbase = bn + wn * 32;       // inside one head (256 | colbase range)
        const int head = colbase >> 8;
#pragma unroll
        for (int i = 0; i < 4; i++) {
            float ps0 = 0.f, ps1 = 0.f, pd0 = 0.f, pd1 = 0.f;
#pragma unroll
            for (int j = 0; j < 4; j++) {
                int col = colbase + j * 8 + lc * 2;
                float a0 = att_s[col], a1 = att_s[col + 1];
                float d0 = att_d[col], d1 = att_d[col + 1];
                ps0 += acc[i][j][0] * a0 + acc[i][j][1] * a1;
                ps1 += acc[i][j][2] * a0 + acc[i][j][3] * a1;
                pd0 += acc[i][j][0] * d0 + acc[i][j][1] * d1;
                pd1 += acc[i][j][2] * d0 + acc[i][j][3] * d1;
            }
            // reduce over the 4 lanes (lc) sharing each row
#pragma unroll
            for (int off = 1; off < 4; off <<= 1) {
                ps0 += __shfl_down_sync(0xffffffffu, ps0, off, 4);
                ps1 += __shfl_down_sync(0xffffffffu, ps1, off, 4);
                pd0 += __shfl_down_sync(0xffffffffu, pd0, off, 4);
                pd1 += __shfl_down_sync(0xffffffffu, pd1, off, 4);
            }
            if (lc == 0) {
                int row0 = bm + wm * 64 + i * 16 + lr;
                atomicAdd(&g_as[row0 * HH + head], ps0);
                atomicAdd(&g_as[(row0 + 8) * HH + head], ps1);
                atomicAdd(&g_ad[row0 * HH + head], pd0);
                atomicAdd(&g_ad[(row0 + 8) * HH + head], pd1);
            }
        }
    }
}

// =================== graph pipeline ==========================================
__global__ void init_kernel() {
    int i = blockIdx.x * blockDim.x + threadIdx.x;
    if (i < MM * HH) {
        g_max[i] = -INFINITY;
        g_den[i] = 0.f;
        g_as[i]  = 0.f;
        g_ad[i]  = 0.f;
    }
    if (i < MM) g_deg[i] = 0;
}

__global__ void round_tf32_k(const float* __restrict__ in, float* __restrict__ out, int n4) {
    int i = blockIdx.x * blockDim.x + threadIdx.x;
    if (i >= n4) return;
    float4 v = reinterpret_cast<const float4*>(in)[i];
    v.x = tf32r(v.x); v.y = tf32r(v.y); v.z = tf32r(v.z); v.w = tf32r(v.w);
    reinterpret_cast<float4*>(out)[i] = v;
}

// per-edge: logits (4 heads, float4), segment max, degree count
__global__ void edge_logits(const int* __restrict__ ei) {
    int t = blockIdx.x * blockDim.x + threadIdx.x;
    if (t >= BB * EL) return;
    int e = t % EL;
    int b = t / EL;
    int src, dst;
    if (e < EE) { src = ei[b * 2 * EE + e]; dst = ei[b * 2 * EE + EE + e]; }
    else        { src = dst = e - EE; }
    atomicAdd(&g_deg[b * LL + dst], 1);
    float4 s = *(const float4*)&g_as[(b * LL + src) * HH];
    float4 d = *(const float4*)&g_ad[(b * LL + dst) * HH];
    float4 v;
    v.x = s.x + d.x; v.x = v.x > 0.f ? v.x : 0.2f * v.x;
    v.y = s.y + d.y; v.y = v.y > 0.f ? v.y : 0.2f * v.y;
    v.z = s.z + d.z; v.z = v.z > 0.f ? v.z : 0.2f * v.z;
    v.w = s.w + d.w; v.w = v.w > 0.f ? v.w : 0.2f * v.w;
    *(float4*)&g_ebuf[t * HH] = v;
    float* mp = &g_max[(b * LL + dst) * HH];
    float vv[4] = {v.x, v.y, v.z, v.w};
#pragma unroll
    for (int h = 0; h < 4; h++) {
        if (vv[h] >= 0.f) atomicMax((int*)(mp + h), __float_as_int(vv[h]));
        else atomicMin((unsigned int*)(mp + h), (unsigned int)__float_as_int(vv[h]));
    }
}

__global__ void __launch_bounds__(1024) scan_k() {
    __shared__ int sp[1024];
    int tid = threadIdx.x;
    int base = tid * 16;
    int loc[16];
    int s = 0;
#pragma unroll
    for (int i = 0; i < 16; i++) { loc[i] = s; s += g_deg[base + i]; }
    sp[tid] = s;
    __syncthreads();
    for (int off = 1; off < 1024; off <<= 1) {
        int v = (tid >= off) ? sp[tid - off] : 0;
        __syncthreads();
        sp[tid] += v;
        __syncthreads();
    }
    int excl = sp[tid] - s;
#pragma unroll
    for (int i = 0; i < 16; i++) {
        g_off[base + i] = excl + loc[i];
        g_cur[base + i] = excl + loc[i];
    }
    if (tid == 1023) g_off[MM] = sp[1023];
}

// fused: CSR scatter + softmax numerator + denominator
__global__ void scatter_softmax(const int* __restrict__ ei) {
    int t = blockIdx.x * blockDim.x + threadIdx.x;
    if (t >= BB * EL) return;
    int e = t % EL;
    int b = t / EL;
    int src, dst;
    if (e < EE) { src = ei[b * 2 * EE + e]; dst = ei[b * 2 * EE + EE + e]; }
    else        { src = dst = e - EE; }
    int node = b * LL + dst;
    int pos = atomicAdd(&g_cur[node], 1);
    g_csr[pos] = src | (e << 10);
    float4 m = *(const float4*)&g_max[node * HH];
    float4 p = *(const float4*)&g_ebuf[t * HH];
    p.x = __expf(p.x - m.x);
    p.y = __expf(p.y - m.y);
    p.z = __expf(p.z - m.z);
    p.w = __expf(p.w - m.w);
    *(float4*)&g_ebuf[t * HH] = p;
    redAdd4(&g_den[node * HH], p);
}

__global__ void __launch_bounds__(256) gather_k(const float* __restrict__ bg) {
    int node = blockIdx.x;
    int b    = node >> 10;
    int tid  = threadIdx.x;
    int c    = tid << 2;
    int head = c >> 8;

    float rden = 1.f / (g_den[node * HH + head] + 1e-16f);
    int start = g_off[node], end = g_off[node + 1];
    const float* hbase = g_h    + (size_t)(b << 10) * HC;
    const float* pbase = g_ebuf + (size_t)b * EL * HH;

    float4 acc = make_float4(0.f, 0.f, 0.f, 0.f);
    for (int i = start; i < end; i++) {
        int v   = g_csr[i];
        int src = v & 1023;
        int eid = v >> 10;
        float alpha = pbase[eid * HH + head] * rden;
        float4 hv = *(const float4*)(hbase + (size_t)src * HC + c);
        acc.x = fmaf(alpha, hv.x, acc.x);
        acc.y = fmaf(alpha, hv.y, acc.y);
        acc.z = fmaf(alpha, hv.z, acc.z);
        acc.w = fmaf(alpha, hv.w, acc.w);
    }
    float4 bb = *(const float4*)&bg[c];
    acc.x = tf32r(acc.x + bb.x); acc.y = tf32r(acc.y + bb.y);
    acc.z = tf32r(acc.z + bb.z); acc.w = tf32r(acc.w + bb.w);
    *(float4*)&g_gatr[(size_t)node * HC + c] = acc;
}

// ---------------- launch ------------------------------------------------------
extern "C" void kernel_launch(void* const* d_in, const int* in_sizes, int n_in,
                              void* d_out, int out_size)
{
    const float* x    = (const float*)d_in[0];
    const int*   ei   = (const int*)  d_in[1];
    const float* Wg   = (const float*)d_in[2];
    const float* asrc = (const float*)d_in[3];
    const float* adst = (const float*)d_in[4];
    const float* bg   = (const float*)d_in[5];
    const float* Wo   = (const float*)d_in[6];
    const float* bo   = (const float*)d_in[7];
    float* out = (float*)d_out;

    float *p_h, *p_xr, *p_gatr, *p_wgr, *p_wor;
    cudaGetSymbolAddress((void**)&p_h,    g_h);
    cudaGetSymbolAddress((void**)&p_xr,   g_xr);
    cudaGetSymbolAddress((void**)&p_gatr, g_gatr);
    cudaGetSymbolAddress((void**)&p_wgr,  g_wgr);
    cudaGetSymbolAddress((void**)&p_wor,  g_wor);

    cudaFuncSetAttribute((const void*)gemm_mma<false, true>,
                         cudaFuncAttributeMaxDynamicSharedMemorySize, GEMM_SMEM);
    cudaFuncSetAttribute((const void*)gemm_mma<true, false>,
                         cudaFuncAttributeMaxDynamicSharedMemorySize, GEMM_SMEM);

    // 1) init
    init_kernel<<<(MM * HH + 255) / 256, 256>>>();

    // 2,3) tf32-round x, W_gat
    round_tf32_k<<<(MM * DD / 4 + 255) / 256, 256>>>(x,  p_xr,  MM * DD / 4);
    round_tf32_k<<<(HC * DD / 4 + 255) / 256, 256>>>(Wg, p_wgr, HC * DD / 4);

    // 4) h = x @ W_gat^T  (+ fused a_s/a_d)   <-- profiled launch slot
    gemm_mma<false, true><<<dim3(HC / 128, MM / 128), 256, GEMM_SMEM>>>(
        p_xr, nullptr, p_wgr, nullptr, asrc, adst, p_h, HC, DD, 0);

    // 5) tf32-round W_out
    round_tf32_k<<<(DD * KOUT / 4 + 255) / 256, 256>>>(Wo, p_wor, DD * KOUT / 4);

    // 6) per-edge logits + segment max + degrees
    edge_logits<<<(BB * EL + 255) / 256, 256>>>(ei);

    // 7) CSR offsets
    scan_k<<<1, 1024>>>();

    // 8) CSR scatter + softmax
    scatter_softmax<<<(BB * EL + 255) / 256, 256>>>(ei);

    // 9) gather aggregate (+bias, tf32 round)
    gather_k<<<MM, 256>>>(bg);

    // 10) out = [x | gat] @ W_out^T + b_out
    gemm_mma<true, false><<<dim3(DD / 128, MM / 128), 256, GEMM_SMEM>>>(
        p_xr, p_gatr, p_wor, bo, nullptr, nullptr, out, DD, KOUT, DD);
}

// round 10
// speedup vs baseline: 1.1085x; 1.1085x over previous
#include <cuda_runtime.h>
#include <cuda_bf16.h>
#include <math.h>
#include <stdint.h>

// Problem constants
#define BB   16
#define LL   1024
#define DD   768
#define HH   4
#define CC   256
#define EE   8192
#define HC   1024           // H*C
#define EL   (EE + LL)      // 9216 edges incl. self loops
#define KOUT (DD + HC)      // 1792
#define MM   (BB * LL)      // 16384

// ---------------- scratch (device globals; no allocation allowed) -----------
__device__ __align__(16) float g_h   [(size_t)MM * HC];   // h = x @ Wg^T (fp32)
__device__ __align__(16) float g_xr  [(size_t)MM * DD];   // tf32-rounded x
__device__ __align__(16) float g_gatr[(size_t)MM * HC];   // tf32-rounded (gat + b_gat)
__device__ __align__(16) float g_wgr [(size_t)HC * DD];   // tf32-rounded W_gat
__device__ __align__(16) float g_wor [(size_t)DD * KOUT]; // tf32-rounded W_out
__device__ __align__(16) float g_as  [MM * HH];
__device__ __align__(16) float g_ad  [MM * HH];
__device__ __align__(16) float g_max [MM * HH];
__device__ __align__(16) float g_den [MM * HH];
__device__ __align__(16) float g_ebuf[BB * EL * HH];      // per-edge probs
__device__ int g_deg[MM];
__device__ int g_off[MM + 1];
__device__ int g_cur[MM];
__device__ int g_csr[BB * EL];     // packed (eid<<10 | src)

// ---------------- helpers ----------------------------------------------------
__device__ __forceinline__ void redAdd4(float* p, float4 v) {
    asm volatile("red.global.add.v4.f32 [%0], {%1,%2,%3,%4};"
                 :: "l"(p), "f"(v.x), "f"(v.y), "f"(v.z), "f"(v.w) : "memory");
}
__device__ __forceinline__ float tf32r(float x) {
    uint32_t u;
    asm("cvt.rna.tf32.f32 %0, %1;" : "=r"(u) : "f"(x));
    return __uint_as_float(u);
}
__device__ __forceinline__ void cp16s(uint32_t sa, const void* g) {
    asm volatile("cp.async.cg.shared.global [%0], [%1], 16;" :: "r"(sa), "l"(g));
}
__device__ __forceinline__ void mma8(float* d, const uint32_t* a, const uint32_t* b) {
    asm volatile(
        "mma.sync.aligned.m16n8k8.row.col.f32.tf32.tf32.f32 "
        "{%0,%1,%2,%3}, {%4,%5,%6,%7}, {%8,%9}, {%0,%1,%2,%3};"
        : "+f"(d[0]), "+f"(d[1]), "+f"(d[2]), "+f"(d[3])
        : "r"(a[0]), "r"(a[1]), "r"(a[2]), "r"(a[3]), "r"(b[0]), "r"(b[1]));
}

// =================== tf32 mma.sync GEMM, 3-stage cp.async ====================
// C[M,N] = A[M,K] * B[N,K]^T (+bias). 128x128 CTA tile, K chunks of 32.
// 8 warps, warp tile 64x32. __launch_bounds__(256,2) forces regs<=128 so
// TWO CTAs co-reside per SM (2 x 110592B smem = 221184 <= 228KB).
#define LDT   36
#define TILEF (128 * LDT)                 // floats per (A or B) tile
#define STGF  (2 * TILEF)                 // floats per stage
#define STGB  (STGF * 4)                  // bytes per stage (36864)
#define GEMM_SMEM (3 * STGB)              // 110592

template<bool SPLIT, bool ATTN>
__global__ void __launch_bounds__(256, 2)
gemm_mma(const float* __restrict__ A, const float* __restrict__ A2,
         const float* __restrict__ Bm, const float* __restrict__ bias,
         const float* __restrict__ att_s, const float* __restrict__ att_d,
         float* __restrict__ C, int N, int K, int K1)
{
    extern __shared__ float sm[];
    const uint32_t sb = (uint32_t)__cvta_generic_to_shared(sm);

    const int tid  = threadIdx.x;
    const int bm   = blockIdx.y * 128;
    const int bn   = blockIdx.x * 128;
    const int lane = tid & 31;
    const int warp = tid >> 5;
    const int wm   = warp & 1;
    const int wn   = warp >> 1;
    const int lr   = lane >> 2;
    const int lc   = lane & 3;

    float acc[4][4][4];
#pragma unroll
    for (int i = 0; i < 4; i++)
#pragma unroll
        for (int j = 0; j < 4; j++)
#pragma unroll
            for (int r = 0; r < 4; r++) acc[i][j][r] = 0.f;

    const int nk = K >> 5;

    auto load_chunk = [&](int st, int kt) {
        const int k0 = kt << 5;
        const float* Ap; int lda, kc;
        if (!SPLIT || k0 < K1) { Ap = A;  lda = SPLIT ? K1 : K; kc = k0; }
        else                   { Ap = A2; lda = K - K1;         kc = k0 - K1; }
        const uint32_t sa = sb + st * STGB;
        const uint32_t sB = sa + TILEF * 4;
#pragma unroll
        for (int t = 0; t < 4; t++) {
            int fid = tid + t * 256;
            int row = fid >> 3;
            int kq  = (fid & 7) << 2;
            uint32_t so = (uint32_t)(row * LDT + kq) * 4u;
            cp16s(sa + so, &Ap[(size_t)(bm + row) * lda + kc + kq]);
            cp16s(sB + so, &Bm[(size_t)(bn + row) * K + k0 + kq]);
        }
    };

    auto compute = [&](int st) {
        const float* sA = sm + st * STGF + (wm * 64 + lr) * LDT + lc;
        const float* sB = sm + st * STGF + TILEF + (wn * 32 + lr) * LDT + lc;
#pragma unroll
        for (int ks = 0; ks < 32; ks += 8) {
            uint32_t af[4][4], bf[4][2];
#pragma unroll
            for (int i = 0; i < 4; i++) {
                const float* p = sA + i * 16 * LDT + ks;
                af[i][0] = __float_as_uint(p[0]);
                af[i][1] = __float_as_uint(p[8 * LDT]);
                af[i][2] = __float_as_uint(p[4]);
                af[i][3] = __float_as_uint(p[8 * LDT + 4]);
            }
#pragma unroll
            for (int j = 0; j < 4; j++) {
                const float* p = sB + j * 8 * LDT + ks;
                bf[j][0] = __float_as_uint(p[0]);
                bf[j][1] = __float_as_uint(p[4]);
            }
#pragma unroll
            for (int i = 0; i < 4; i++)
#pragma unroll
                for (int j = 0; j < 4; j++)
                    mma8(acc[i][j], af[i], bf[j]);
        }
    };

    // 3-stage pipeline, one barrier per chunk
    load_chunk(0, 0);
    asm volatile("cp.async.commit_group;");
    load_chunk(1, 1);
    asm volatile("cp.async.commit_group;");

    int cs = 0, ls = 2;
    for (int it = 0; it < nk; ++it) {
        asm volatile("cp.async.wait_group 1;");
        __syncthreads();
        if (it + 2 < nk) load_chunk(ls, it + 2);
        asm volatile("cp.async.commit_group;");
        compute(cs);
        if (++cs == 3) cs = 0;
        if (++ls == 3) ls = 0;
    }

    // ---- epilogue: C write (+bias) ----
#pragma unroll
    for (int j = 0; j < 4; j++) {
        int col = bn + wn * 32 + j * 8 + lc * 2;
        float b0 = bias ? bias[col] : 0.f;
        float b1 = bias ? bias[col + 1] : 0.f;
#pragma unroll
        for (int i = 0; i < 4; i++) {
            int row0 = bm + wm * 64 + i * 16 + lr;
            float2 v0 = make_float2(acc[i][j][0] + b0, acc[i][j][1] + b1);
            float2 v1 = make_float2(acc[i][j][2] + b0, acc[i][j][3] + b1);
            *(float2*)&C[(size_t)row0 * N + col]       = v0;
            *(float2*)&C[(size_t)(row0 + 8) * N + col] = v1;
        }
    }

    // ---- fused attention dots ----
    if (ATTN) {
        const int colbase = bn + wn * 32;
        const int head = colbase >> 8;
#pragma unroll
        for (int i = 0; i < 4; i++) {
            float ps0 = 0.f, ps1 = 0.f, pd0 = 0.f, pd1 = 0.f;
#pragma unroll
            for (int j = 0; j < 4; j++) {
                int col = colbase + j * 8 + lc * 2;
                float a0 = att_s[col], a1 = att_s[col + 1];
                float d0 = att_d[col], d1 = att_d[col + 1];
                ps0 += acc[i][j][0] * a0 + acc[i][j][1] * a1;
                ps1 += acc[i][j][2] * a0 + acc[i][j][3] * a1;
                pd0 += acc[i][j][0] * d0 + acc[i][j][1] * d1;
                pd1 += acc[i][j][2] * d0 + acc[i][j][3] * d1;
            }
#pragma unroll
            for (int off = 1; off < 4; off <<= 1) {
                ps0 += __shfl_down_sync(0xffffffffu, ps0, off, 4);
                ps1 += __shfl_down_sync(0xffffffffu, ps1, off, 4);
                pd0 += __shfl_down_sync(0xffffffffu, pd0, off, 4);
                pd1 += __shfl_down_sync(0xffffffffu, pd1, off, 4);
            }
            if (lc == 0) {
                int row0 = bm + wm * 64 + i * 16 + lr;
                atomicAdd(&g_as[row0 * HH + head], ps0);
                atomicAdd(&g_as[(row0 + 8) * HH + head], ps1);
                atomicAdd(&g_ad[row0 * HH + head], pd0);
                atomicAdd(&g_ad[(row0 + 8) * HH + head], pd1);
            }
        }
    }
}

// =================== graph pipeline ==========================================
__global__ void init_kernel() {
    int i = blockIdx.x * blockDim.x + threadIdx.x;
    if (i < MM * HH) {
        g_max[i] = -INFINITY;
        g_den[i] = 0.f;
        g_as[i]  = 0.f;
        g_ad[i]  = 0.f;
    }
    if (i < MM) g_deg[i] = 0;
}

__global__ void round_tf32_k(const float* __restrict__ in, float* __restrict__ out, int n4) {
    int i = blockIdx.x * blockDim.x + threadIdx.x;
    if (i >= n4) return;
    float4 v = reinterpret_cast<const float4*>(in)[i];
    v.x = tf32r(v.x); v.y = tf32r(v.y); v.z = tf32r(v.z); v.w = tf32r(v.w);
    reinterpret_cast<float4*>(out)[i] = v;
}

__global__ void edge_logits(const int* __restrict__ ei) {
    int t = blockIdx.x * blockDim.x + threadIdx.x;
    if (t >= BB * EL) return;
    int e = t % EL;
    int b = t / EL;
    int src, dst;
    if (e < EE) { src = ei[b * 2 * EE + e]; dst = ei[b * 2 * EE + EE + e]; }
    else        { src = dst = e - EE; }
    atomicAdd(&g_deg[b * LL + dst], 1);
    float4 s = *(const float4*)&g_as[(b * LL + src) * HH];
    float4 d = *(const float4*)&g_ad[(b * LL + dst) * HH];
    float4 v;
    v.x = s.x + d.x; v.x = v.x > 0.f ? v.x : 0.2f * v.x;
    v.y = s.y + d.y; v.y = v.y > 0.f ? v.y : 0.2f * v.y;
    v.z = s.z + d.z; v.z = v.z > 0.f ? v.z : 0.2f * v.z;
    v.w = s.w + d.w; v.w = v.w > 0.f ? v.w : 0.2f * v.w;
    *(float4*)&g_ebuf[t * HH] = v;
    float* mp = &g_max[(b * LL + dst) * HH];
    float vv[4] = {v.x, v.y, v.z, v.w};
#pragma unroll
    for (int h = 0; h < 4; h++) {
        if (vv[h] >= 0.f) atomicMax((int*)(mp + h), __float_as_int(vv[h]));
        else atomicMin((unsigned int*)(mp + h), (unsigned int)__float_as_int(vv[h]));
    }
}

__global__ void __launch_bounds__(1024) scan_k() {
    __shared__ int sp[1024];
    int tid = threadIdx.x;
    int base = tid * 16;
    int loc[16];
    int s = 0;
#pragma unroll
    for (int i = 0; i < 16; i++) { loc[i] = s; s += g_deg[base + i]; }
    sp[tid] = s;
    __syncthreads();
    for (int off = 1; off < 1024; off <<= 1) {
        int v = (tid >= off) ? sp[tid - off] : 0;
        __syncthreads();
        sp[tid] += v;
        __syncthreads();
    }
    int excl = sp[tid] - s;
#pragma unroll
    for (int i = 0; i < 16; i++) {
        g_off[base + i] = excl + loc[i];
        g_cur[base + i] = excl + loc[i];
    }
    if (tid == 1023) g_off[MM] = sp[1023];
}

__global__ void scatter_softmax(const int* __restrict__ ei) {
    int t = blockIdx.x * blockDim.x + threadIdx.x;
    if (t >= BB * EL) return;
    int e = t % EL;
    int b = t / EL;
    int src, dst;
    if (e < EE) { src = ei[b * 2 * EE + e]; dst = ei[b * 2 * EE + EE + e]; }
    else        { src = dst = e - EE; }
    int node = b * LL + dst;
    int pos = atomicAdd(&g_cur[node], 1);
    g_csr[pos] = src | (e << 10);
    float4 m = *(const float4*)&g_max[node * HH];
    float4 p = *(const float4*)&g_ebuf[t * HH];
    p.x = __expf(p.x - m.x);
    p.y = __expf(p.y - m.y);
    p.z = __expf(p.z - m.z);
    p.w = __expf(p.w - m.w);
    *(float4*)&g_ebuf[t * HH] = p;
    redAdd4(&g_den[node * HH], p);
}

__global__ void __launch_bounds__(256) gather_k(const float* __restrict__ bg) {
    int node = blockIdx.x;
    int b    = node >> 10;
    int tid  = threadIdx.x;
    int c    = tid << 2;
    int head = c >> 8;

    float rden = 1.f / (g_den[node * HH + head] + 1e-16f);
    int start = g_off[node], end = g_off[node + 1];
    const float* hbase = g_h    + (size_t)(b << 10) * HC;
    const float* pbase = g_ebuf + (size_t)b * EL * HH;

    float4 acc = make_float4(0.f, 0.f, 0.f, 0.f);
    for (int i = start; i < end; i++) {
        int v   = g_csr[i];
        int src = v & 1023;
        int eid = v >> 10;
        float alpha = pbase[eid * HH + head] * rden;
        float4 hv = *(const float4*)(hbase + (size_t)src * HC + c);
        acc.x = fmaf(alpha, hv.x, acc.x);
        acc.y = fmaf(alpha, hv.y, acc.y);
        acc.z = fmaf(alpha, hv.z, acc.z);
        acc.w = fmaf(alpha, hv.w, acc.w);
    }
    float4 bb = *(const float4*)&bg[c];
    acc.x = tf32r(acc.x + bb.x); acc.y = tf32r(acc.y + bb.y);
    acc.z = tf32r(acc.z + bb.z); acc.w = tf32r(acc.w + bb.w);
    *(float4*)&g_gatr[(size_t)node * HC + c] = acc;
}

// ---------------- launch ------------------------------------------------------
extern "C" void kernel_launch(void* const* d_in, const int* in_sizes, int n_in,
                              void* d_out, int out_size)
{
    const float* x    = (const float*)d_in[0];
    const int*   ei   = (const int*)  d_in[1];
    const float* Wg   = (const float*)d_in[2];
    const float* asrc = (const float*)d_in[3];
    const float* adst = (const float*)d_in[4];
    const float* bg   = (const float*)d_in[5];
    const float* Wo   = (const float*)d_in[6];
    const float* bo   = (const float*)d_in[7];
    float* out = (float*)d_out;

    float *p_h, *p_xr, *p_gatr, *p_wgr, *p_wor;
    cudaGetSymbolAddress((void**)&p_h,    g_h);
    cudaGetSymbolAddress((void**)&p_xr,   g_xr);
    cudaGetSymbolAddress((void**)&p_gatr, g_gatr);
    cudaGetSymbolAddress((void**)&p_wgr,  g_wgr);
    cudaGetSymbolAddress((void**)&p_wor,  g_wor);

    cudaFuncSetAttribute((const void*)gemm_mma<false, true>,
                         cudaFuncAttributeMaxDynamicSharedMemorySize, GEMM_SMEM);
    cudaFuncSetAttribute((const void*)gemm_mma<true, false>,
                         cudaFuncAttributeMaxDynamicSharedMemorySize, GEMM_SMEM);

    // 1) init
    init_kernel<<<(MM * HH + 255) / 256, 256>>>();

    // 2,3) tf32-round x, W_gat
    round_tf32_k<<<(MM * DD / 4 + 255) / 256, 256>>>(x,  p_xr,  MM * DD / 4);
    round_tf32_k<<<(HC * DD / 4 + 255) / 256, 256>>>(Wg, p_wgr, HC * DD / 4);

    // 4) h = x @ W_gat^T  (+ fused a_s/a_d)   <-- profiled launch slot
    gemm_mma<false, true><<<dim3(HC / 128, MM / 128), 256, GEMM_SMEM>>>(
        p_xr, nullptr, p_wgr, nullptr, asrc, adst, p_h, HC, DD, 0);

    // 5) tf32-round W_out
    round_tf32_k<<<(DD * KOUT / 4 + 255) / 256, 256>>>(Wo, p_wor, DD * KOUT / 4);

    // 6) per-edge logits + segment max + degrees
    edge_logits<<<(BB * EL + 255) / 256, 256>>>(ei);

    // 7) CSR offsets
    scan_k<<<1, 1024>>>();

    // 8) CSR scatter + softmax
    scatter_softmax<<<(BB * EL + 255) / 256, 256>>>(ei);

    // 9) gather aggregate (+bias, tf32 round)
    gather_k<<<MM, 256>>>(bg);

    // 10) out = [x | gat] @ W_out^T + b_out
    gemm_mma<true, false><<<dim3(DD / 128, MM / 128), 256, GEMM_SMEM>>>(
        p_xr, p_gatr, p_wor, bo, nullptr, nullptr, out, DD, KOUT, DD);
}

// round 15
// speedup vs baseline: 1.1821x; 1.0664x over previous
#include <cuda_runtime.h>
#include <cuda_bf16.h>
#include <math.h>
#include <stdint.h>

// Problem constants
#define BB   16
#define LL   1024
#define DD   768
#define HH   4
#define CC   256
#define EE   8192
#define HC   1024           // H*C
#define EL   (EE + LL)      // 9216 edges incl. self loops
#define KOUT (DD + HC)      // 1792
#define MM   (BB * LL)      // 16384

// ---------------- scratch (device globals; no allocation allowed) -----------
__device__ __align__(16) float g_h   [(size_t)MM * HC];   // h = x @ Wg^T (fp32)
__device__ __align__(16) float g_xr  [(size_t)MM * DD];   // tf32-rounded x
__device__ __align__(16) float g_gatr[(size_t)MM * HC];   // tf32-rounded (gat + b_gat)
__device__ __align__(16) float g_wgr [(size_t)HC * DD];   // tf32-rounded W_gat
__device__ __align__(16) float g_wor [(size_t)DD * KOUT]; // tf32-rounded W_out
__device__ __align__(16) float g_as  [MM * HH];
__device__ __align__(16) float g_ad  [MM * HH];
__device__ __align__(16) float g_max [MM * HH];
__device__ __align__(16) float g_den [MM * HH];
__device__ __align__(16) float g_ebuf[BB * EL * HH];      // per-edge probs
__device__ int g_deg[MM];
__device__ int g_off[MM + 1];
__device__ int g_cur[MM];
__device__ int g_csr[BB * EL];     // packed (eid<<10 | src)

// ---------------- helpers ----------------------------------------------------
__device__ __forceinline__ void redAdd4(float* p, float4 v) {
    asm volatile("red.global.add.v4.f32 [%0], {%1,%2,%3,%4};"
                 :: "l"(p), "f"(v.x), "f"(v.y), "f"(v.z), "f"(v.w) : "memory");
}
__device__ __forceinline__ float tf32r(float x) {
    uint32_t u;
    asm("cvt.rna.tf32.f32 %0, %1;" : "=r"(u) : "f"(x));
    return __uint_as_float(u);
}
__device__ __forceinline__ void cp16s(uint32_t sa, const void* g) {
    asm volatile("cp.async.cg.shared.global [%0], [%1], 16;" :: "r"(sa), "l"(g));
}
__device__ __forceinline__ void mma8(float* d, const uint32_t* a, const uint32_t* b) {
    asm volatile(
        "mma.sync.aligned.m16n8k8.row.col.f32.tf32.tf32.f32 "
        "{%0,%1,%2,%3}, {%4,%5,%6,%7}, {%8,%9}, {%0,%1,%2,%3};"
        : "+f"(d[0]), "+f"(d[1]), "+f"(d[2]), "+f"(d[3])
        : "r"(a[0]), "r"(a[1]), "r"(a[2]), "r"(a[3]), "r"(b[0]), "r"(b[1]));
}

// =================== tf32 mma.sync GEMM, 3-stage cp.async ====================
// C[M,N] = A[M,K] * B[N,K]^T (+bias). 128x128 CTA tile, K chunks of 32.
// 8 warps, warp tile 64x32. Smem rows are 128B (32 tf32) with a per-row
// granule swizzle swz(r)=((r&1)<<2)|(r>>1); fragment loads are LDS.128 using
// a k-permutation (legal: same (lane,slot)->k map for A and B, row-independent).
#define STGF  (2 * 128 * 32)              // floats per stage (A tile + B tile)
#define STGB  (STGF * 4)                  // 32768 bytes per stage
#define GEMM_SMEM (3 * STGB)              // 98304

__device__ __forceinline__ int swzf(int r) { return ((r & 1) << 2) | (r >> 1); }

template<bool SPLIT, bool ATTN>
__global__ void __launch_bounds__(256, 2)
gemm_mma(const float* __restrict__ A, const float* __restrict__ A2,
         const float* __restrict__ Bm, const float* __restrict__ bias,
         const float* __restrict__ att_s, const float* __restrict__ att_d,
         float* __restrict__ C, int N, int K, int K1)
{
    extern __shared__ float sm[];
    const uint32_t sb = (uint32_t)__cvta_generic_to_shared(sm);

    const int tid  = threadIdx.x;
    const int bm   = blockIdx.y * 128;
    const int bn   = blockIdx.x * 128;
    const int lane = tid & 31;
    const int warp = tid >> 5;
    const int wm   = warp & 1;
    const int wn   = warp >> 1;
    const int lr   = lane >> 2;
    const int lc   = lane & 3;

    float acc[4][4][4];
#pragma unroll
    for (int i = 0; i < 4; i++)
#pragma unroll
        for (int j = 0; j < 4; j++)
#pragma unroll
            for (int r = 0; r < 4; r++) acc[i][j][r] = 0.f;

    const int nk = K >> 5;

    auto load_chunk = [&](int st, int kt) {
        const int k0 = kt << 5;
        const float* Ap; int lda, kc;
        if (!SPLIT || k0 < K1) { Ap = A;  lda = SPLIT ? K1 : K; kc = k0; }
        else                   { Ap = A2; lda = K - K1;         kc = k0 - K1; }
        const uint32_t sa = sb + st * STGB;
        const uint32_t sB = sa + 128 * 128;      // A tile is 128 rows * 128B
#pragma unroll
        for (int t = 0; t < 4; t++) {
            int fid = tid + t * 256;
            int row = fid >> 3;
            int c   = fid & 7;
            uint32_t so = (uint32_t)(row * 128 + ((c ^ swzf(row & 7)) << 4));
            cp16s(sa + so, &Ap[(size_t)(bm + row) * lda + kc + c * 4]);
            cp16s(sB + so, &Bm[(size_t)(bn + row) * K + k0 + c * 4]);
        }
    };

    const int swzv = swzf(lr);
    auto compute = [&](int st) {
        const float* Ab = sm + st * STGF + (wm * 64 + lr) * 32;
        const float* Bb = sm + st * STGF + 128 * 32 + (wn * 32 + lr) * 32;
#pragma unroll
        for (int mp = 0; mp < 2; mp++) {
            const int gOff = ((lc + 4 * mp) ^ swzv) << 2;   // float offset in row
            float4 B4[4];
#pragma unroll
            for (int j = 0; j < 4; j++)
                B4[j] = *(const float4*)(Bb + j * 8 * 32 + gOff);
#pragma unroll
            for (int i = 0; i < 4; i++) {
                float4 A0 = *(const float4*)(Ab + i * 16 * 32 + gOff);
                float4 A1 = *(const float4*)(Ab + (i * 16 + 8) * 32 + gOff);
                uint32_t af[4], bf[2];
                af[0] = __float_as_uint(A0.x); af[1] = __float_as_uint(A1.x);
                af[2] = __float_as_uint(A0.y); af[3] = __float_as_uint(A1.y);
#pragma unroll
                for (int j = 0; j < 4; j++) {
                    bf[0] = __float_as_uint(B4[j].x);
                    bf[1] = __float_as_uint(B4[j].y);
                    mma8(acc[i][j], af, bf);
                }
                af[0] = __float_as_uint(A0.z); af[1] = __float_as_uint(A1.z);
                af[2] = __float_as_uint(A0.w); af[3] = __float_as_uint(A1.w);
#pragma unroll
                for (int j = 0; j < 4; j++) {
                    bf[0] = __float_as_uint(B4[j].z);
                    bf[1] = __float_as_uint(B4[j].w);
                    mma8(acc[i][j], af, bf);
                }
            }
        }
    };

    // 3-stage pipeline, one barrier per chunk
    load_chunk(0, 0);
    asm volatile("cp.async.commit_group;");
    load_chunk(1, 1);
    asm volatile("cp.async.commit_group;");

    int cs = 0, ls = 2;
    for (int it = 0; it < nk; ++it) {
        asm volatile("cp.async.wait_group 1;");
        __syncthreads();
        if (it + 2 < nk) load_chunk(ls, it + 2);
        asm volatile("cp.async.commit_group;");
        compute(cs);
        if (++cs == 3) cs = 0;
        if (++ls == 3) ls = 0;
    }

    // ---- epilogue: C write (+bias) ----
#pragma unroll
    for (int j = 0; j < 4; j++) {
        int col = bn + wn * 32 + j * 8 + lc * 2;
        float b0 = bias ? bias[col] : 0.f;
        float b1 = bias ? bias[col + 1] : 0.f;
#pragma unroll
        for (int i = 0; i < 4; i++) {
            int row0 = bm + wm * 64 + i * 16 + lr;
            float2 v0 = make_float2(acc[i][j][0] + b0, acc[i][j][1] + b1);
            float2 v1 = make_float2(acc[i][j][2] + b0, acc[i][j][3] + b1);
            *(float2*)&C[(size_t)row0 * N + col]       = v0;
            *(float2*)&C[(size_t)(row0 + 8) * N + col] = v1;
        }
    }

    // ---- fused attention dots ----
    if (ATTN) {
        const int colbase = bn + wn * 32;
        const int head = colbase >> 8;
#pragma unroll
        for (int i = 0; i < 4; i++) {
            float ps0 = 0.f, ps1 = 0.f, pd0 = 0.f, pd1 = 0.f;
#pragma unroll
            for (int j = 0; j < 4; j++) {
                int col = colbase + j * 8 + lc * 2;
                float a0 = att_s[col], a1 = att_s[col + 1];
                float d0 = att_d[col], d1 = att_d[col + 1];
                ps0 += acc[i][j][0] * a0 + acc[i][j][1] * a1;
                ps1 += acc[i][j][2] * a0 + acc[i][j][3] * a1;
                pd0 += acc[i][j][0] * d0 + acc[i][j][1] * d1;
                pd1 += acc[i][j][2] * d0 + acc[i][j][3] * d1;
            }
#pragma unroll
            for (int off = 1; off < 4; off <<= 1) {
                ps0 += __shfl_down_sync(0xffffffffu, ps0, off, 4);
                ps1 += __shfl_down_sync(0xffffffffu, ps1, off, 4);
                pd0 += __shfl_down_sync(0xffffffffu, pd0, off, 4);
                pd1 += __shfl_down_sync(0xffffffffu, pd1, off, 4);
            }
            if (lc == 0) {
                int row0 = bm + wm * 64 + i * 16 + lr;
                atomicAdd(&g_as[row0 * HH + head], ps0);
                atomicAdd(&g_as[(row0 + 8) * HH + head], ps1);
                atomicAdd(&g_ad[row0 * HH + head], pd0);
                atomicAdd(&g_ad[(row0 + 8) * HH + head], pd1);
            }
        }
    }
}

// =================== graph pipeline ==========================================
__global__ void init_kernel() {
    int i = blockIdx.x * blockDim.x + threadIdx.x;
    if (i < MM * HH) {
        g_max[i] = -INFINITY;
        g_den[i] = 0.f;
        g_as[i]  = 0.f;
        g_ad[i]  = 0.f;
    }
    if (i < MM) g_deg[i] = 0;
}

__global__ void round_tf32_k(const float* __restrict__ in, float* __restrict__ out, int n4) {
    int i = blockIdx.x * blockDim.x + threadIdx.x;
    if (i >= n4) return;
    float4 v = reinterpret_cast<const float4*>(in)[i];
    v.x = tf32r(v.x); v.y = tf32r(v.y); v.z = tf32r(v.z); v.w = tf32r(v.w);
    reinterpret_cast<float4*>(out)[i] = v;
}

__global__ void edge_logits(const int* __restrict__ ei) {
    int t = blockIdx.x * blockDim.x + threadIdx.x;
    if (t >= BB * EL) return;
    int e = t % EL;
    int b = t / EL;
    int src, dst;
    if (e < EE) { src = ei[b * 2 * EE + e]; dst = ei[b * 2 * EE + EE + e]; }
    else        { src = dst = e - EE; }
    atomicAdd(&g_deg[b * LL + dst], 1);
    float4 s = *(const float4*)&g_as[(b * LL + src) * HH];
    float4 d = *(const float4*)&g_ad[(b * LL + dst) * HH];
    float4 v;
    v.x = s.x + d.x; v.x = v.x > 0.f ? v.x : 0.2f * v.x;
    v.y = s.y + d.y; v.y = v.y > 0.f ? v.y : 0.2f * v.y;
    v.z = s.z + d.z; v.z = v.z > 0.f ? v.z : 0.2f * v.z;
    v.w = s.w + d.w; v.w = v.w > 0.f ? v.w : 0.2f * v.w;
    *(float4*)&g_ebuf[t * HH] = v;
    float* mp = &g_max[(b * LL + dst) * HH];
    float vv[4] = {v.x, v.y, v.z, v.w};
#pragma unroll
    for (int h = 0; h < 4; h++) {
        if (vv[h] >= 0.f) atomicMax((int*)(mp + h), __float_as_int(vv[h]));
        else atomicMin((unsigned int*)(mp + h), (unsigned int)__float_as_int(vv[h]));
    }
}

__global__ void __launch_bounds__(1024) scan_k() {
    __shared__ int sp[1024];
    int tid = threadIdx.x;
    int base = tid * 16;
    int loc[16];
    int s = 0;
#pragma unroll
    for (int i = 0; i < 16; i++) { loc[i] = s; s += g_deg[base + i]; }
    sp[tid] = s;
    __syncthreads();
    for (int off = 1; off < 1024; off <<= 1) {
        int v = (tid >= off) ? sp[tid - off] : 0;
        __syncthreads();
        sp[tid] += v;
        __syncthreads();
    }
    int excl = sp[tid] - s;
#pragma unroll
    for (int i = 0; i < 16; i++) {
        g_off[base + i] = excl + loc[i];
        g_cur[base + i] = excl + loc[i];
    }
    if (tid == 1023) g_off[MM] = sp[1023];
}

__global__ void scatter_softmax(const int* __restrict__ ei) {
    int t = blockIdx.x * blockDim.x + threadIdx.x;
    if (t >= BB * EL) return;
    int e = t % EL;
    int b = t / EL;
    int src, dst;
    if (e < EE) { src = ei[b * 2 * EE + e]; dst = ei[b * 2 * EE + EE + e]; }
    else        { src = dst = e - EE; }
    int node = b * LL + dst;
    int pos = atomicAdd(&g_cur[node], 1);
    g_csr[pos] = src | (e << 10);
    float4 m = *(const float4*)&g_max[node * HH];
    float4 p = *(const float4*)&g_ebuf[t * HH];
    p.x = __expf(p.x - m.x);
    p.y = __expf(p.y - m.y);
    p.z = __expf(p.z - m.z);
    p.w = __expf(p.w - m.w);
    *(float4*)&g_ebuf[t * HH] = p;
    redAdd4(&g_den[node * HH], p);
}

__global__ void __launch_bounds__(256) gather_k(const float* __restrict__ bg) {
    int node = blockIdx.x;
    int b    = node >> 10;
    int tid  = threadIdx.x;
    int c    = tid << 2;
    int head = c >> 8;

    float rden = 1.f / (g_den[node * HH + head] + 1e-16f);
    int start = g_off[node], end = g_off[node + 1];
    const float* hbase = g_h    + (size_t)(b << 10) * HC;
    const float* pbase = g_ebuf + (size_t)b * EL * HH;

    float4 acc = make_float4(0.f, 0.f, 0.f, 0.f);
    for (int i = start; i < end; i++) {
        int v   = g_csr[i];
        int src = v & 1023;
        int eid = v >> 10;
        float alpha = pbase[eid * HH + head] * rden;
        float4 hv = *(const float4*)(hbase + (size_t)src * HC + c);
        acc.x = fmaf(alpha, hv.x, acc.x);
        acc.y = fmaf(alpha, hv.y, acc.y);
        acc.z = fmaf(alpha, hv.z, acc.z);
        acc.w = fmaf(alpha, hv.w, acc.w);
    }
    float4 bb = *(const float4*)&bg[c];
    acc.x = tf32r(acc.x + bb.x); acc.y = tf32r(acc.y + bb.y);
    acc.z = tf32r(acc.z + bb.z); acc.w = tf32r(acc.w + bb.w);
    *(float4*)&g_gatr[(size_t)node * HC + c] = acc;
}

// ---------------- launch ------------------------------------------------------
extern "C" void kernel_launch(void* const* d_in, const int* in_sizes, int n_in,
                              void* d_out, int out_size)
{
    const float* x    = (const float*)d_in[0];
    const int*   ei   = (const int*)  d_in[1];
    const float* Wg   = (const float*)d_in[2];
    const float* asrc = (const float*)d_in[3];
    const float* adst = (const float*)d_in[4];
    const float* bg   = (const float*)d_in[5];
    const float* Wo   = (const float*)d_in[6];
    const float* bo   = (const float*)d_in[7];
    float* out = (float*)d_out;

    float *p_h, *p_xr, *p_gatr, *p_wgr, *p_wor;
    cudaGetSymbolAddress((void**)&p_h,    g_h);
    cudaGetSymbolAddress((void**)&p_xr,   g_xr);
    cudaGetSymbolAddress((void**)&p_gatr, g_gatr);
    cudaGetSymbolAddress((void**)&p_wgr,  g_wgr);
    cudaGetSymbolAddress((void**)&p_wor,  g_wor);

    cudaFuncSetAttribute((const void*)gemm_mma<false, true>,
                         cudaFuncAttributeMaxDynamicSharedMemorySize, GEMM_SMEM);
    cudaFuncSetAttribute((const void*)gemm_mma<true, false>,
                         cudaFuncAttributeMaxDynamicSharedMemorySize, GEMM_SMEM);

    // 1) init
    init_kernel<<<(MM * HH + 255) / 256, 256>>>();

    // 2,3) tf32-round x, W_gat
    round_tf32_k<<<(MM * DD / 4 + 255) / 256, 256>>>(x,  p_xr,  MM * DD / 4);
    round_tf32_k<<<(HC * DD / 4 + 255) / 256, 256>>>(Wg, p_wgr, HC * DD / 4);

    // 4) h = x @ W_gat^T  (+ fused a_s/a_d)   <-- profiled launch slot
    gemm_mma<false, true><<<dim3(HC / 128, MM / 128), 256, GEMM_SMEM>>>(
        p_xr, nullptr, p_wgr, nullptr, asrc, adst, p_h, HC, DD, 0);

    // 5) tf32-round W_out
    round_tf32_k<<<(DD * KOUT / 4 + 255) / 256, 256>>>(Wo, p_wor, DD * KOUT / 4);

    // 6) per-edge logits + segment max + degrees
    edge_logits<<<(BB * EL + 255) / 256, 256>>>(ei);

    // 7) CSR offsets
    scan_k<<<1, 1024>>>();

    // 8) CSR scatter + softmax
    scatter_softmax<<<(BB * EL + 255) / 256, 256>>>(ei);

    // 9) gather aggregate (+bias, tf32 round)
    gather_k<<<MM, 256>>>(bg);

    // 10) out = [x | gat] @ W_out^T + b_out
    gemm_mma<true, false><<<dim3(DD / 128, MM / 128), 256, GEMM_SMEM>>>(
        p_xr, p_gatr, p_wor, bo, nullptr, nullptr, out, DD, KOUT, DD);
}

// round 17
// speedup vs baseline: 1.2368x; 1.0463x over previous
#include <cuda_runtime.h>
#include <cuda_bf16.h>
#include <math.h>
#include <stdint.h>

// Problem constants
#define BB   16
#define LL   1024
#define DD   768
#define HH   4
#define CC   256
#define EE   8192
#define HC   1024           // H*C
#define EL   (EE + LL)      // 9216 edges incl. self loops
#define KOUT (DD + HC)      // 1792
#define MM   (BB * LL)      // 16384

// ---------------- scratch (device globals; no allocation allowed) -----------
__device__ __align__(16) float g_h   [(size_t)MM * HC];   // h = x @ Wg^T (fp32)
__device__ __align__(16) float g_xr  [(size_t)MM * DD];   // tf32-rounded x
__device__ __align__(16) float g_gatr[(size_t)MM * HC];   // tf32-rounded (gat + b_gat)
__device__ __align__(16) float g_wgr [(size_t)HC * DD];   // tf32-rounded W_gat
__device__ __align__(16) float g_wor [(size_t)DD * KOUT]; // tf32-rounded W_out
__device__ __align__(16) float g_as  [MM * HH];
__device__ __align__(16) float g_ad  [MM * HH];
__device__ __align__(16) float g_max [MM * HH];
__device__ __align__(16) float g_den [MM * HH];
__device__ __align__(16) float g_ebuf[BB * EL * HH];      // per-edge probs
__device__ int g_deg[MM];
__device__ int g_off[MM + 1];
__device__ int g_cur[MM];
__device__ int g_csr[BB * EL];     // packed (eid<<10 | src)

// ---------------- helpers ----------------------------------------------------
__device__ __forceinline__ void redAdd4(float* p, float4 v) {
    asm volatile("red.global.add.v4.f32 [%0], {%1,%2,%3,%4};"
                 :: "l"(p), "f"(v.x), "f"(v.y), "f"(v.z), "f"(v.w) : "memory");
}
__device__ __forceinline__ float tf32r(float x) {
    uint32_t u;
    asm("cvt.rna.tf32.f32 %0, %1;" : "=r"(u) : "f"(x));
    return __uint_as_float(u);
}
__device__ __forceinline__ void cp16s(uint32_t sa, const void* g) {
    asm volatile("cp.async.cg.shared.global [%0], [%1], 16;" :: "r"(sa), "l"(g));
}
__device__ __forceinline__ void mma8(float* d, const uint32_t* a, const uint32_t* b) {
    asm volatile(
        "mma.sync.aligned.m16n8k8.row.col.f32.tf32.tf32.f32 "
        "{%0,%1,%2,%3}, {%4,%5,%6,%7}, {%8,%9}, {%0,%1,%2,%3};"
        : "+f"(d[0]), "+f"(d[1]), "+f"(d[2]), "+f"(d[3])
        : "r"(a[0]), "r"(a[1]), "r"(a[2]), "r"(a[3]), "r"(b[0]), "r"(b[1]));
}

// =================== tf32 mma.sync GEMM, 3-stage cp.async ====================
// C[M,N] = A[M,K] * B[N,K]^T (+bias). 128x128 CTA tile, K chunks of 32.
// 8 warps, warp tile 64x32. Smem rows 128B, per-row granule swizzle
// swz(r)=((r&1)<<2)|(r>>1); LDS.128 fragment loads via k-permutation.
// Mainloop unrolled by 3 so ALL stage bases are compile-time constants
// (kills the IMAD/LEA address storm seen at 31% alu in R15).
#define STGF  (2 * 128 * 32)              // floats per stage (A tile + B tile)
#define STGB  (STGF * 4)                  // 32768 bytes per stage
#define GEMM_SMEM (3 * STGB)              // 98304

__device__ __forceinline__ int swzf(int r) { return ((r & 1) << 2) | (r >> 1); }

template<bool SPLIT, bool ATTN>
__global__ void __launch_bounds__(256, 2)
gemm_mma(const float* __restrict__ A, const float* __restrict__ A2,
         const float* __restrict__ Bm, const float* __restrict__ bias,
         const float* __restrict__ att_s, const float* __restrict__ att_d,
         float* __restrict__ C, int N, int K, int K1)
{
    extern __shared__ float sm[];
    const uint32_t sb = (uint32_t)__cvta_generic_to_shared(sm);

    const int tid  = threadIdx.x;
    const int bm   = blockIdx.y * 128;
    const int bn   = blockIdx.x * 128;
    const int lane = tid & 31;
    const int warp = tid >> 5;
    const int wm   = warp & 1;
    const int wn   = warp >> 1;
    const int lr   = lane >> 2;
    const int lc   = lane & 3;

    float acc[4][4][4];
#pragma unroll
    for (int i = 0; i < 4; i++)
#pragma unroll
        for (int j = 0; j < 4; j++)
#pragma unroll
            for (int r = 0; r < 4; r++) acc[i][j][r] = 0.f;

    const int nk = K >> 5;

    // row/granule for this thread's fill slots (loop-invariant)
    const int frow = tid >> 3;             // rows covered: frow, frow+32, +64, +96
    const int fc   = tid & 7;

    auto load_chunk = [&](int st, int kt) {   // st is a constant at call sites below
        const int k0 = kt << 5;
        const float* Ap; int lda, kc;
        if (!SPLIT || k0 < K1) { Ap = A;  lda = SPLIT ? K1 : K; kc = k0; }
        else                   { Ap = A2; lda = K - K1;         kc = k0 - K1; }
        const uint32_t sa = sb + st * STGB;
        const uint32_t sB = sa + 128 * 128;
#pragma unroll
        for (int t = 0; t < 4; t++) {
            int row = frow + t * 32;
            uint32_t so = (uint32_t)(row * 128 + ((fc ^ swzf(row & 7)) << 4));
            cp16s(sa + so, &Ap[(size_t)(bm + row) * lda + kc + fc * 4]);
            cp16s(sB + so, &Bm[(size_t)(bn + row) * K + k0 + fc * 4]);
        }
    };

    const int swzv = swzf(lr);
    const int aoff = (wm * 64 + lr) * 32;
    const int boff = 128 * 32 + (wn * 32 + lr) * 32;

    auto compute = [&](int st) {             // st constant at call sites
        const float* Ab = sm + st * STGF + aoff;
        const float* Bb = sm + st * STGF + boff;
#pragma unroll
        for (int mp = 0; mp < 2; mp++) {
            const int gOff = ((lc + 4 * mp) ^ swzv) << 2;
            float4 B4[4];
#pragma unroll
            for (int j = 0; j < 4; j++)
                B4[j] = *(const float4*)(Bb + j * 8 * 32 + gOff);
#pragma unroll
            for (int i = 0; i < 4; i++) {
                float4 A0 = *(const float4*)(Ab + i * 16 * 32 + gOff);
                float4 A1 = *(const float4*)(Ab + (i * 16 + 8) * 32 + gOff);
                uint32_t af[4], bf[2];
                af[0] = __float_as_uint(A0.x); af[1] = __float_as_uint(A1.x);
                af[2] = __float_as_uint(A0.y); af[3] = __float_as_uint(A1.y);
#pragma unroll
                for (int j = 0; j < 4; j++) {
                    bf[0] = __float_as_uint(B4[j].x);
                    bf[1] = __float_as_uint(B4[j].y);
                    mma8(acc[i][j], af, bf);
                }
                af[0] = __float_as_uint(A0.z); af[1] = __float_as_uint(A1.z);
                af[2] = __float_as_uint(A0.w); af[3] = __float_as_uint(A1.w);
#pragma unroll
                for (int j = 0; j < 4; j++) {
                    bf[0] = __float_as_uint(B4[j].z);
                    bf[1] = __float_as_uint(B4[j].w);
                    mma8(acc[i][j], af, bf);
                }
            }
        }
    };

    auto step = [&](int it, int cs, int ls) {  // cs/ls literal at call sites
        asm volatile("cp.async.wait_group 1;");
        __syncthreads();
        if (it + 2 < nk) load_chunk(ls, it + 2);
        asm volatile("cp.async.commit_group;");
        compute(cs);
    };

    load_chunk(0, 0);
    asm volatile("cp.async.commit_group;");
    load_chunk(1, 1);
    asm volatile("cp.async.commit_group;");

    int it = 0;
    for (; it + 3 <= nk; it += 3) {          // stages fully constant inside
        step(it + 0, 0, 2);
        step(it + 1, 1, 0);
        step(it + 2, 2, 1);
    }
    // tail (<=2 iterations; cs provably 0 here, ls 2)
    {
        int cs = 0, ls = 2;
        for (; it < nk; ++it) {
            step(it, cs, ls);
            if (++cs == 3) cs = 0;
            if (++ls == 3) ls = 0;
        }
    }

    // ---- epilogue: C write (+bias) ----
#pragma unroll
    for (int j = 0; j < 4; j++) {
        int col = bn + wn * 32 + j * 8 + lc * 2;
        float b0 = bias ? bias[col] : 0.f;
        float b1 = bias ? bias[col + 1] : 0.f;
#pragma unroll
        for (int i = 0; i < 4; i++) {
            int row0 = bm + wm * 64 + i * 16 + lr;
            float2 v0 = make_float2(acc[i][j][0] + b0, acc[i][j][1] + b1);
            float2 v1 = make_float2(acc[i][j][2] + b0, acc[i][j][3] + b1);
            *(float2*)&C[(size_t)row0 * N + col]       = v0;
            *(float2*)&C[(size_t)(row0 + 8) * N + col] = v1;
        }
    }

    // ---- fused attention dots ----
    if (ATTN) {
        const int colbase = bn + wn * 32;
        const int head = colbase >> 8;
#pragma unroll
        for (int i = 0; i < 4; i++) {
            float ps0 = 0.f, ps1 = 0.f, pd0 = 0.f, pd1 = 0.f;
#pragma unroll
            for (int j = 0; j < 4; j++) {
                int col = colbase + j * 8 + lc * 2;
                float a0 = att_s[col], a1 = att_s[col + 1];
                float d0 = att_d[col], d1 = att_d[col + 1];
                ps0 += acc[i][j][0] * a0 + acc[i][j][1] * a1;
                ps1 += acc[i][j][2] * a0 + acc[i][j][3] * a1;
                pd0 += acc[i][j][0] * d0 + acc[i][j][1] * d1;
                pd1 += acc[i][j][2] * d0 + acc[i][j][3] * d1;
            }
#pragma unroll
            for (int off = 1; off < 4; off <<= 1) {
                ps0 += __shfl_down_sync(0xffffffffu, ps0, off, 4);
                ps1 += __shfl_down_sync(0xffffffffu, ps1, off, 4);
                pd0 += __shfl_down_sync(0xffffffffu, pd0, off, 4);
                pd1 += __shfl_down_sync(0xffffffffu, pd1, off, 4);
            }
            if (lc == 0) {
                int row0 = bm + wm * 64 + i * 16 + lr;
                atomicAdd(&g_as[row0 * HH + head], ps0);
                atomicAdd(&g_as[(row0 + 8) * HH + head], ps1);
                atomicAdd(&g_ad[row0 * HH + head], pd0);
                atomicAdd(&g_ad[(row0 + 8) * HH + head], pd1);
            }
        }
    }
}

// =================== graph pipeline ==========================================
__global__ void init_kernel() {
    int i = blockIdx.x * blockDim.x + threadIdx.x;
    if (i < MM * HH) {
        g_max[i] = -INFINITY;
        g_den[i] = 0.f;
        g_as[i]  = 0.f;
        g_ad[i]  = 0.f;
    }
    if (i < MM) g_deg[i] = 0;
}

__global__ void round_tf32_k(const float* __restrict__ in, float* __restrict__ out, int n4) {
    int i = blockIdx.x * blockDim.x + threadIdx.x;
    if (i >= n4) return;
    float4 v = reinterpret_cast<const float4*>(in)[i];
    v.x = tf32r(v.x); v.y = tf32r(v.y); v.z = tf32r(v.z); v.w = tf32r(v.w);
    reinterpret_cast<float4*>(out)[i] = v;
}

__global__ void edge_logits(const int* __restrict__ ei) {
    int t = blockIdx.x * blockDim.x + threadIdx.x;
    if (t >= BB * EL) return;
    int e = t % EL;
    int b = t / EL;
    int src, dst;
    if (e < EE) { src = ei[b * 2 * EE + e]; dst = ei[b * 2 * EE + EE + e]; }
    else        { src = dst = e - EE; }
    atomicAdd(&g_deg[b * LL + dst], 1);
    float4 s = *(const float4*)&g_as[(b * LL + src) * HH];
    float4 d = *(const float4*)&g_ad[(b * LL + dst) * HH];
    float4 v;
    v.x = s.x + d.x; v.x = v.x > 0.f ? v.x : 0.2f * v.x;
    v.y = s.y + d.y; v.y = v.y > 0.f ? v.y : 0.2f * v.y;
    v.z = s.z + d.z; v.z = v.z > 0.f ? v.z : 0.2f * v.z;
    v.w = s.w + d.w; v.w = v.w > 0.f ? v.w : 0.2f * v.w;
    *(float4*)&g_ebuf[t * HH] = v;
    float* mp = &g_max[(b * LL + dst) * HH];
    float vv[4] = {v.x, v.y, v.z, v.w};
#pragma unroll
    for (int h = 0; h < 4; h++) {
        if (vv[h] >= 0.f) atomicMax((int*)(mp + h), __float_as_int(vv[h]));
        else atomicMin((unsigned int*)(mp + h), (unsigned int)__float_as_int(vv[h]));
    }
}

__global__ void __launch_bounds__(1024) scan_k() {
    __shared__ int sp[1024];
    int tid = threadIdx.x;
    int base = tid * 16;
    int loc[16];
    int s = 0;
#pragma unroll
    for (int i = 0; i < 16; i++) { loc[i] = s; s += g_deg[base + i]; }
    sp[tid] = s;
    __syncthreads();
    for (int off = 1; off < 1024; off <<= 1) {
        int v = (tid >= off) ? sp[tid - off] : 0;
        __syncthreads();
        sp[tid] += v;
        __syncthreads();
    }
    int excl = sp[tid] - s;
#pragma unroll
    for (int i = 0; i < 16; i++) {
        g_off[base + i] = excl + loc[i];
        g_cur[base + i] = excl + loc[i];
    }
    if (tid == 1023) g_off[MM] = sp[1023];
}

__global__ void scatter_softmax(const int* __restrict__ ei) {
    int t = blockIdx.x * blockDim.x + threadIdx.x;
    if (t >= BB * EL) return;
    int e = t % EL;
    int b = t / EL;
    int src, dst;
    if (e < EE) { src = ei[b * 2 * EE + e]; dst = ei[b * 2 * EE + EE + e]; }
    else        { src = dst = e - EE; }
    int node = b * LL + dst;
    int pos = atomicAdd(&g_cur[node], 1);
    g_csr[pos] = src | (e << 10);
    float4 m = *(const float4*)&g_max[node * HH];
    float4 p = *(const float4*)&g_ebuf[t * HH];
    p.x = __expf(p.x - m.x);
    p.y = __expf(p.y - m.y);
    p.z = __expf(p.z - m.z);
    p.w = __expf(p.w - m.w);
    *(float4*)&g_ebuf[t * HH] = p;
    redAdd4(&g_den[node * HH], p);
}

__global__ void __launch_bounds__(256) gather_k(const float* __restrict__ bg) {
    int node = blockIdx.x;
    int b    = node >> 10;
    int tid  = threadIdx.x;
    int c    = tid << 2;
    int head = c >> 8;

    float rden = 1.f / (g_den[node * HH + head] + 1e-16f);
    int start = g_off[node], end = g_off[node + 1];
    const float* hbase = g_h    + (size_t)(b << 10) * HC;
    const float* pbase = g_ebuf + (size_t)b * EL * HH;

    float4 acc = make_float4(0.f, 0.f, 0.f, 0.f);
    for (int i = start; i < end; i++) {
        int v   = g_csr[i];
        int src = v & 1023;
        int eid = v >> 10;
        float alpha = pbase[eid * HH + head] * rden;
        float4 hv = *(const float4*)(hbase + (size_t)src * HC + c);
        acc.x = fmaf(alpha, hv.x, acc.x);
        acc.y = fmaf(alpha, hv.y, acc.y);
        acc.z = fmaf(alpha, hv.z, acc.z);
        acc.w = fmaf(alpha, hv.w, acc.w);
    }
    float4 bb = *(const float4*)&bg[c];
    acc.x = tf32r(acc.x + bb.x); acc.y = tf32r(acc.y + bb.y);
    acc.z = tf32r(acc.z + bb.z); acc.w = tf32r(acc.w + bb.w);
    *(float4*)&g_gatr[(size_t)node * HC + c] = acc;
}

// ---------------- launch ------------------------------------------------------
extern "C" void kernel_launch(void* const* d_in, const int* in_sizes, int n_in,
                              void* d_out, int out_size)
{
    const float* x    = (const float*)d_in[0];
    const int*   ei   = (const int*)  d_in[1];
    const float* Wg   = (const float*)d_in[2];
    const float* asrc = (const float*)d_in[3];
    const float* adst = (const float*)d_in[4];
    const float* bg   = (const float*)d_in[5];
    const float* Wo   = (const float*)d_in[6];
    const float* bo   = (const float*)d_in[7];
    float* out = (float*)d_out;

    float *p_h, *p_xr, *p_gatr, *p_wgr, *p_wor;
    cudaGetSymbolAddress((void**)&p_h,    g_h);
    cudaGetSymbolAddress((void**)&p_xr,   g_xr);
    cudaGetSymbolAddress((void**)&p_gatr, g_gatr);
    cudaGetSymbolAddress((void**)&p_wgr,  g_wgr);
    cudaGetSymbolAddress((void**)&p_wor,  g_wor);

    cudaFuncSetAttribute((const void*)gemm_mma<false, true>,
                         cudaFuncAttributeMaxDynamicSharedMemorySize, GEMM_SMEM);
    cudaFuncSetAttribute((const void*)gemm_mma<true, false>,
                         cudaFuncAttributeMaxDynamicSharedMemorySize, GEMM_SMEM);

    // 1) init
    init_kernel<<<(MM * HH + 255) / 256, 256>>>();

    // 2,3) tf32-round x, W_gat
    round_tf32_k<<<(MM * DD / 4 + 255) / 256, 256>>>(x,  p_xr,  MM * DD / 4);
    round_tf32_k<<<(HC * DD / 4 + 255) / 256, 256>>>(Wg, p_wgr, HC * DD / 4);

    // 4) h = x @ W_gat^T  (+ fused a_s/a_d)   <-- profiled launch slot
    gemm_mma<false, true><<<dim3(HC / 128, MM / 128), 256, GEMM_SMEM>>>(
        p_xr, nullptr, p_wgr, nullptr, asrc, adst, p_h, HC, DD, 0);

    // 5) tf32-round W_out
    round_tf32_k<<<(DD * KOUT / 4 + 255) / 256, 256>>>(Wo, p_wor, DD * KOUT / 4);

    // 6) per-edge logits + segment max + degrees
    edge_logits<<<(BB * EL + 255) / 256, 256>>>(ei);

    // 7) CSR offsets
    scan_k<<<1, 1024>>>();

    // 8) CSR scatter + softmax
    scatter_softmax<<<(BB * EL + 255) / 256, 256>>>(ei);

    // 9) gather aggregate (+bias, tf32 round)
    gather_k<<<MM, 256>>>(bg);

    // 10) out = [x | gat] @ W_out^T + b_out
    gemm_mma<true, false><<<dim3(DD / 128, MM / 128), 256, GEMM_SMEM>>>(
        p_xr, p_gatr, p_wor, bo, nullptr, nullptr, out, DD, KOUT, DD);
}